// round 1
// baseline (speedup 1.0000x reference)
#include <cuda_runtime.h>
#include <cuda_bf16.h>
#include <cstdint>
#include <cstddef>

// ---------------------------------------------------------------------------
// Attention: B=32, N=1024, D=512, fp32 in/out.
//   q = X @ Wq^T ; k = X @ Wk^T ; v = X @ Wv^T
//   S = q k^T / sqrt(512) ; S[S==0] = 1e-10 ; P = softmax(S) ; O = P v
// Strategy: tf32 mma.sync GEMMs (fp32 accumulate) + row softmax.
// ---------------------------------------------------------------------------

#define B_BATCH 32
#define N_SEQ   1024
#define DIM     512
#define M_TOT   (B_BATCH * N_SEQ)          // 32768
#define QKV_STRIDE ((size_t)M_TOT * DIM)   // 16777216 floats per q/k/v plane
#define BATCH_QKV  ((size_t)N_SEQ * DIM)   // 524288
#define BATCH_S    ((size_t)N_SEQ * N_SEQ) // 1048576

// Scratch (static device globals: allowed; no runtime allocation)
__device__ float g_qkv[3 * QKV_STRIDE];    // [3][32768][512]
__device__ float g_s[B_BATCH * BATCH_S];   // [32][1024][1024]

// ---- PTX helpers ----------------------------------------------------------
__device__ __forceinline__ uint32_t f2tf(float x) {
    uint32_t r;
    asm("cvt.rna.tf32.f32 %0, %1;" : "=r"(r) : "f"(x));
    return r;
}

__device__ __forceinline__ void mma_16x8x8(float* c, const uint32_t* a,
                                           uint32_t b0, uint32_t b1) {
    asm volatile(
        "mma.sync.aligned.m16n8k8.row.col.f32.tf32.tf32.f32 "
        "{%0,%1,%2,%3}, {%4,%5,%6,%7}, {%8,%9}, {%0,%1,%2,%3};"
        : "+f"(c[0]), "+f"(c[1]), "+f"(c[2]), "+f"(c[3])
        : "r"(a[0]), "r"(a[1]), "r"(a[2]), "r"(a[3]), "r"(b0), "r"(b1));
}

#define CP16(dst_u32, src_ptr) \
    asm volatile("cp.async.cg.shared.global [%0], [%1], 16;" :: "r"(dst_u32), "l"(src_ptr))
#define CP_COMMIT() asm volatile("cp.async.commit_group;")
#define CP_WAIT0()  asm volatile("cp.async.wait_group 0;")
#define CP_WAIT1()  asm volatile("cp.async.wait_group 1;")

// ---- Tiled GEMM body ------------------------------------------------------
// C[M,N] = alpha * A[M,K] * op(B),  A row-major (K contiguous).
// BT=true : B is [N,K] row-major (K contiguous)  -> "NT" (C=A*B^T)
// BT=false: B is [K,N] row-major (N contiguous)  -> "NN" (C=A*B)
// Block tile 128x128x32, 256 threads, 8 warps (4 in M x 2 in N), warp 32x64.
// Smem layout (floats):
//   As: [2 bufs][128][36]  (pad 4 -> conflict-free fragment loads)
//   Bs NT: [2][128][36];  Bs NN: [2][32][132]
#define AS_STRIDE 36
#define AS_BUF    (128 * AS_STRIDE)   // 4608
#define BSN_STRIDE 132
#define BSN_BUF   (32 * BSN_STRIDE)   // 4224
#define SMEM_FLOATS (2 * AS_BUF + 2 * AS_BUF)   // worst case (NT) = 18432
#define SMEM_BYTES  (SMEM_FLOATS * 4)           // 73728

template<bool BT>
__device__ __forceinline__ void gemm_body(const float* __restrict__ A,
                                          const float* __restrict__ B,
                                          float* __restrict__ C,
                                          int lda, int ldb, int ldc,
                                          int K, float alpha) {
    extern __shared__ float smem[];
    float* As = smem;
    float* Bs = smem + 2 * AS_BUF;

    const int tid  = threadIdx.x;
    const int bm   = blockIdx.x * 128;
    const int bn   = blockIdx.y * 128;
    const int lane = tid & 31;
    const int wid  = tid >> 5;
    const int wm0  = (wid & 3) * 32;
    const int wn0  = (wid >> 2) * 64;
    const int g    = lane >> 2;   // 0..7
    const int t4   = lane & 3;    // 0..3

    const uint32_t as_u = (uint32_t)__cvta_generic_to_shared(As);
    const uint32_t bs_u = (uint32_t)__cvta_generic_to_shared(Bs);

    float acc[2][8][4];
#pragma unroll
    for (int i = 0; i < 2; i++)
#pragma unroll
        for (int j = 0; j < 8; j++)
#pragma unroll
            for (int r = 0; r < 4; r++) acc[i][j][r] = 0.0f;

    // --- async tile loaders ---
    auto loadA = [&](int kt, int buf) {
#pragma unroll
        for (int i = 0; i < 4; i++) {
            int c  = tid + i * 256;       // 0..1023 chunks of 4 floats
            int r  = c >> 3;              // 0..127
            int c4 = (c & 7) * 4;         // 0..28
            uint32_t dst = as_u + (uint32_t)((buf * AS_BUF + r * AS_STRIDE + c4) * 4);
            const float* src = A + (size_t)(bm + r) * lda + kt * 32 + c4;
            CP16(dst, src);
        }
    };
    auto loadB = [&](int kt, int buf) {
#pragma unroll
        for (int i = 0; i < 4; i++) {
            int c = tid + i * 256;
            if (BT) {
                int r  = c >> 3;
                int c4 = (c & 7) * 4;
                uint32_t dst = bs_u + (uint32_t)((buf * AS_BUF + r * AS_STRIDE + c4) * 4);
                const float* src = B + (size_t)(bn + r) * ldb + kt * 32 + c4;
                CP16(dst, src);
            } else {
                int r  = c >> 5;              // 0..31 (k rows)
                int c4 = (c & 31) * 4;        // 0..124 (n cols)
                uint32_t dst = bs_u + (uint32_t)((buf * BSN_BUF + r * BSN_STRIDE + c4) * 4);
                const float* src = B + (size_t)(kt * 32 + r) * ldb + bn + c4;
                CP16(dst, src);
            }
        }
    };

    auto compute = [&](int buf) {
        const float* Ab = As + buf * AS_BUF;
        const float* Bb = Bs + buf * (BT ? AS_BUF : BSN_BUF);
#pragma unroll
        for (int ks = 0; ks < 4; ks++) {
            const int k0 = ks * 8;
            uint32_t af[2][4];
#pragma unroll
            for (int i = 0; i < 2; i++) {
                int r = wm0 + i * 16 + g;
                af[i][0] = f2tf(Ab[r * AS_STRIDE + k0 + t4]);
                af[i][1] = f2tf(Ab[(r + 8) * AS_STRIDE + k0 + t4]);
                af[i][2] = f2tf(Ab[r * AS_STRIDE + k0 + t4 + 4]);
                af[i][3] = f2tf(Ab[(r + 8) * AS_STRIDE + k0 + t4 + 4]);
            }
#pragma unroll
            for (int j = 0; j < 8; j++) {
                const int n = wn0 + j * 8 + g;
                uint32_t b0, b1;
                if (BT) {
                    b0 = f2tf(Bb[n * AS_STRIDE + k0 + t4]);
                    b1 = f2tf(Bb[n * AS_STRIDE + k0 + t4 + 4]);
                } else {
                    b0 = f2tf(Bb[(k0 + t4) * BSN_STRIDE + n]);
                    b1 = f2tf(Bb[(k0 + t4 + 4) * BSN_STRIDE + n]);
                }
#pragma unroll
                for (int i = 0; i < 2; i++) mma_16x8x8(acc[i][j], af[i], b0, b1);
            }
        }
    };

    // --- mainloop: double-buffered cp.async ---
    const int KT = K >> 5;
    loadA(0, 0); loadB(0, 0); CP_COMMIT();
    for (int kt = 0; kt < KT; kt++) {
        const int buf = kt & 1;
        if (kt + 1 < KT) {
            loadA(kt + 1, buf ^ 1); loadB(kt + 1, buf ^ 1); CP_COMMIT();
            CP_WAIT1();
        } else {
            CP_WAIT0();
        }
        __syncthreads();
        compute(buf);
        __syncthreads();
    }

    // --- epilogue ---
#pragma unroll
    for (int i = 0; i < 2; i++) {
#pragma unroll
        for (int j = 0; j < 8; j++) {
            const int r0 = bm + wm0 + i * 16 + g;
            const int c0 = bn + wn0 + j * 8 + 2 * t4;
            float2 v0 = make_float2(acc[i][j][0] * alpha, acc[i][j][1] * alpha);
            float2 v1 = make_float2(acc[i][j][2] * alpha, acc[i][j][3] * alpha);
            *(float2*)&C[(size_t)r0 * ldc + c0] = v0;
            *(float2*)&C[(size_t)(r0 + 8) * ldc + c0] = v1;
        }
    }
}

// ---- kernels --------------------------------------------------------------
__global__ void __launch_bounds__(256)
qkv_kernel(const float* __restrict__ X, const float* __restrict__ Wq,
           const float* __restrict__ Wk, const float* __restrict__ Wv) {
    const int z = blockIdx.z;                 // 0=q, 1=k, 2=v
    const float* W = (z == 0) ? Wq : (z == 1) ? Wk : Wv;
    gemm_body<true>(X, W, g_qkv + (size_t)z * QKV_STRIDE,
                    DIM, DIM, DIM, DIM, 1.0f);
}

__global__ void __launch_bounds__(256)
scores_kernel() {
    const int z = blockIdx.z;                 // batch
    gemm_body<true>(g_qkv + (size_t)z * BATCH_QKV,                 // Q[b]
                    g_qkv + QKV_STRIDE + (size_t)z * BATCH_QKV,    // K[b]
                    g_s + (size_t)z * BATCH_S,
                    DIM, DIM, N_SEQ, DIM, 0.044194173824159216f);  // 1/sqrt(512)
}

__global__ void __launch_bounds__(128)
softmax_kernel() {
    const size_t row = blockIdx.x;            // 0..32767
    float* p = g_s + row * N_SEQ;
    const int tid = threadIdx.x;              // 128 threads, 8 floats each

    float4 a = ((const float4*)p)[tid];
    float4 b = ((const float4*)p)[tid + 128];
    float v[8] = {a.x, a.y, a.z, a.w, b.x, b.y, b.z, b.w};

    // reference quirk: exact-zero scores -> 1e-10 before softmax
#pragma unroll
    for (int i = 0; i < 8; i++) if (v[i] == 0.0f) v[i] = 1e-10f;

    float mx = v[0];
#pragma unroll
    for (int i = 1; i < 8; i++) mx = fmaxf(mx, v[i]);
#pragma unroll
    for (int o = 16; o > 0; o >>= 1) mx = fmaxf(mx, __shfl_xor_sync(0xffffffffu, mx, o));
    __shared__ float red[4];
    const int wid = tid >> 5, lane = tid & 31;
    if (lane == 0) red[wid] = mx;
    __syncthreads();
    mx = fmaxf(fmaxf(red[0], red[1]), fmaxf(red[2], red[3]));
    __syncthreads();

    float e[8], s = 0.0f;
#pragma unroll
    for (int i = 0; i < 8; i++) { e[i] = __expf(v[i] - mx); s += e[i]; }
#pragma unroll
    for (int o = 16; o > 0; o >>= 1) s += __shfl_xor_sync(0xffffffffu, s, o);
    if (lane == 0) red[wid] = s;
    __syncthreads();
    s = red[0] + red[1] + red[2] + red[3];
    const float inv = 1.0f / s;

    float4 oa = make_float4(e[0] * inv, e[1] * inv, e[2] * inv, e[3] * inv);
    float4 ob = make_float4(e[4] * inv, e[5] * inv, e[6] * inv, e[7] * inv);
    ((float4*)p)[tid] = oa;
    ((float4*)p)[tid + 128] = ob;
}

__global__ void __launch_bounds__(256)
pv_kernel(float* __restrict__ out) {
    const int z = blockIdx.z;                 // batch
    gemm_body<false>(g_s + (size_t)z * BATCH_S,                     // P[b] [1024,1024]
                     g_qkv + 2 * QKV_STRIDE + (size_t)z * BATCH_QKV,// V[b] [1024,512] (NN)
                     out + (size_t)z * BATCH_QKV,
                     N_SEQ, DIM, DIM, N_SEQ, 1.0f);
}

// ---- launch ---------------------------------------------------------------
extern "C" void kernel_launch(void* const* d_in, const int* in_sizes, int n_in,
                              void* d_out, int out_size) {
    const float* X  = (const float*)d_in[0];
    const float* Wq = (const float*)d_in[1];
    const float* Wk = (const float*)d_in[2];
    const float* Wv = (const float*)d_in[3];
    float* out = (float*)d_out;

    // >48KB dynamic smem opt-in (idempotent, not a stream op, no allocation)
    cudaFuncSetAttribute(qkv_kernel,    cudaFuncAttributeMaxDynamicSharedMemorySize, SMEM_BYTES);
    cudaFuncSetAttribute(scores_kernel, cudaFuncAttributeMaxDynamicSharedMemorySize, SMEM_BYTES);
    cudaFuncSetAttribute(pv_kernel,     cudaFuncAttributeMaxDynamicSharedMemorySize, SMEM_BYTES);

    dim3 g1(M_TOT / 128, DIM / 128, 3);       // (256, 4, 3)
    qkv_kernel<<<g1, 256, SMEM_BYTES>>>(X, Wq, Wk, Wv);

    dim3 g2(N_SEQ / 128, N_SEQ / 128, B_BATCH); // (8, 8, 32)
    scores_kernel<<<g2, 256, SMEM_BYTES>>>();

    softmax_kernel<<<M_TOT, 128>>>();         // one block per score row

    dim3 g4(N_SEQ / 128, DIM / 128, B_BATCH); // (8, 4, 32)
    pv_kernel<<<g4, 256, SMEM_BYTES>>>(out);
}